// round 16
// baseline (speedup 1.0000x reference)
#include <cuda_runtime.h>
#include <cuda_bf16.h>
#include <math.h>

// Problem constants
#define B_  8
#define C_  256
#define T_  32
#define HW_ 784            // 28*28
#define HW4_ 196           // HW/4
#define HID_ 512
#define EMB_ 32
#define NBINS_ 4
#define SCALE_ 5.0f

// Scratch (device globals — no allocation allowed)
__device__ float g_pooled[B_ * C_ * T_];   // [B,C,T]
__device__ float g_h[B_ * HID_ * T_];      // [B,HID,T]
__device__ float g_nw[B_ * T_ * NBINS_];   // [B,T,4] => float4 per (b,t)

// ---------------------------------------------------------------------------
// Kernel 1 (R14-exact): spatial mean pool. One warp per (b,c,t) row, __ldcs.
// ---------------------------------------------------------------------------
__global__ void pool_kernel(const float* __restrict__ x) {
    int warp = (blockIdx.x * blockDim.x + threadIdx.x) >> 5;
    int lane = threadIdx.x & 31;
    const float4* row = reinterpret_cast<const float4*>(x) + (size_t)warp * HW4_;
    float4 v0 = __ldcs(&row[lane]);
    float4 v1 = __ldcs(&row[lane + 32]);
    float4 v2 = __ldcs(&row[lane + 64]);
    float4 v3 = __ldcs(&row[lane + 96]);
    float4 v4 = __ldcs(&row[lane + 128]);
    float4 v5 = __ldcs(&row[lane + 160]);
    float4 v6 = (lane < 4) ? __ldcs(&row[lane + 192]) : make_float4(0.f, 0.f, 0.f, 0.f);
    float s = (v0.x + v0.y) + (v0.z + v0.w);
    s += (v1.x + v1.y) + (v1.z + v1.w);
    s += (v2.x + v2.y) + (v2.z + v2.w);
    s += (v3.x + v3.y) + (v3.z + v3.w);
    s += (v4.x + v4.y) + (v4.z + v4.w);
    s += (v5.x + v5.y) + (v5.z + v5.w);
    s += (v6.x + v6.y) + (v6.z + v6.w);
#pragma unroll
    for (int o = 16; o > 0; o >>= 1) s += __shfl_xor_sync(0xFFFFFFFFu, s, o);
    if (lane == 0) g_pooled[warp] = s * (1.0f / (float)HW_);
}

// ---------------------------------------------------------------------------
// Kernel 2a (R14-exact, PDL): h = hswish(W1 @ pooled + b1).
// ---------------------------------------------------------------------------
__global__ __launch_bounds__(1024)
void mlp1_kernel(const float* __restrict__ W1, const float* __restrict__ b1) {
    __shared__ float sp[C_ * T_];    // 32 KB
    __shared__ float sw[32 * C_];    // 32 KB
    int b = blockIdx.x >> 4;                 // /16
    int hid0 = (blockIdx.x & 15) * 32;
    int tid = threadIdx.x;
    {
        const float4* src = reinterpret_cast<const float4*>(W1 + (size_t)hid0 * C_);
        float4* dst = reinterpret_cast<float4*>(sw);
        dst[tid] = src[tid];
        dst[tid + 1024] = src[tid + 1024];
    }
    cudaGridDependencySynchronize();   // wait for pool_kernel
    {
        const float4* src = reinterpret_cast<const float4*>(g_pooled + (size_t)b * C_ * T_);
        float4* dst = reinterpret_cast<float4*>(sp);
        dst[tid] = src[tid];
        dst[tid + 1024] = src[tid + 1024];
    }
    __syncthreads();

    int w = tid >> 5;
    int lane = tid & 31;
    int hid = hid0 + w;
    const float* wr = sw + w * C_;
    float a0 = 0.f, a1 = 0.f, a2 = 0.f, a3 = 0.f;
#pragma unroll 8
    for (int c = 0; c < C_; c += 4) {
        float4 wv = *reinterpret_cast<const float4*>(wr + c);
        a0 = fmaf(wv.x, sp[(c + 0) * T_ + lane], a0);
        a1 = fmaf(wv.y, sp[(c + 1) * T_ + lane], a1);
        a2 = fmaf(wv.z, sp[(c + 2) * T_ + lane], a2);
        a3 = fmaf(wv.w, sp[(c + 3) * T_ + lane], a3);
    }
    float acc = ((a0 + a1) + (a2 + a3)) + b1[hid];
    float g = fminf(fmaxf(acc + 3.0f, 0.0f), 6.0f);
    acc = acc * g * (1.0f / 6.0f);
    g_h[((size_t)b * HID_ + hid) * T_ + lane] = acc;
}

// ---------------------------------------------------------------------------
// Kernel 2b (R14-exact, PDL).
// ---------------------------------------------------------------------------
extern __shared__ float dynsm[];   // [0:16384)=h [hid][t], [16384:32768)=W2 [e][hh]

__global__ __launch_bounds__(1024, 1)
void weights_kernel(const float* __restrict__ W2, const float* __restrict__ b2) {
    __shared__ float ne[EMB_][T_ + 1];
    __shared__ float invn[T_];
    __shared__ float nsv[T_];
    __shared__ float thresh;
    __shared__ int   grp[T_];
    __shared__ float csum[EMB_][NBINS_];
    __shared__ float gsize[NBINS_];
    __shared__ float ncen[EMB_][NBINS_];
    __shared__ float wts[T_][NBINS_];
    __shared__ float sscale[NBINS_];

    int b = blockIdx.x;
    int tid = threadIdx.x;
    float* sh  = dynsm;
    float* sw2 = dynsm + HID_ * T_;

    {
        const float4* wsrc = reinterpret_cast<const float4*>(W2);
        float4* wdst = reinterpret_cast<float4*>(sw2);
#pragma unroll
        for (int i = 0; i < 4; i++) wdst[tid + i * 1024] = wsrc[tid + i * 1024];
    }
    cudaGridDependencySynchronize();   // wait for mlp1_kernel
    {
        const float4* hsrc = reinterpret_cast<const float4*>(g_h + (size_t)b * HID_ * T_);
        float4* hdst = reinterpret_cast<float4*>(sh);
#pragma unroll
        for (int i = 0; i < 4; i++) hdst[tid + i * 1024] = hsrc[tid + i * 1024];
    }
    __syncthreads();

    if (tid < 256) {
        int t = tid & 31;
        int eg = tid >> 5;
        float a0 = 0.f, a1 = 0.f, a2 = 0.f, a3 = 0.f;
        const float* w0 = sw2 + (size_t)(4 * eg + 0) * HID_;
        const float* w1 = sw2 + (size_t)(4 * eg + 1) * HID_;
        const float* w2r = sw2 + (size_t)(4 * eg + 2) * HID_;
        const float* w3 = sw2 + (size_t)(4 * eg + 3) * HID_;
#pragma unroll 4
        for (int hh = 0; hh < HID_; hh += 4) {
            float h0 = sh[(hh + 0) * T_ + t];
            float h1 = sh[(hh + 1) * T_ + t];
            float h2 = sh[(hh + 2) * T_ + t];
            float h3 = sh[(hh + 3) * T_ + t];
            float4 w0v = *reinterpret_cast<const float4*>(w0 + hh);
            float4 w1v = *reinterpret_cast<const float4*>(w1 + hh);
            float4 w2v = *reinterpret_cast<const float4*>(w2r + hh);
            float4 w3v = *reinterpret_cast<const float4*>(w3 + hh);
            a0 = fmaf(w0v.x, h0, a0); a0 = fmaf(w0v.y, h1, a0);
            a0 = fmaf(w0v.z, h2, a0); a0 = fmaf(w0v.w, h3, a0);
            a1 = fmaf(w1v.x, h0, a1); a1 = fmaf(w1v.y, h1, a1);
            a1 = fmaf(w1v.z, h2, a1); a1 = fmaf(w1v.w, h3, a1);
            a2 = fmaf(w2v.x, h0, a2); a2 = fmaf(w2v.y, h1, a2);
            a2 = fmaf(w2v.z, h2, a2); a2 = fmaf(w2v.w, h3, a2);
            a3 = fmaf(w3v.x, h0, a3); a3 = fmaf(w3v.y, h1, a3);
            a3 = fmaf(w3v.z, h2, a3); a3 = fmaf(w3v.w, h3, a3);
        }
        ne[4 * eg + 0][t] = a0 + b2[4 * eg + 0];
        ne[4 * eg + 1][t] = a1 + b2[4 * eg + 1];
        ne[4 * eg + 2][t] = a2 + b2[4 * eg + 2];
        ne[4 * eg + 3][t] = a3 + b2[4 * eg + 3];
    }
    __syncthreads();

    if (tid < T_) {
        float s = 0.0f;
        for (int ee = 0; ee < EMB_; ee++) { float v = ne[ee][tid]; s += v * v; }
        invn[tid] = 1.0f / fmaxf(sqrtf(s), 1e-12f);
    }
    __syncthreads();
    {
        int e = tid >> 5, t = tid & 31;
        ne[e][t] *= invn[t];
    }
    __syncthreads();

    if (tid < T_ - 1) {
        float s = 0.0f;
        for (int ee = 0; ee < EMB_; ee++) s += ne[ee][tid + 1] * ne[ee][tid];
        nsv[tid] = s;
    }
    __syncthreads();

    if (tid < T_ - 1) {
        float v = nsv[tid];
        int cnt = 0;
        for (int j = 0; j < T_ - 1; j++) {
            float o = nsv[j];
            cnt += (o < v) || (o == v && j < tid);
        }
        if (cnt == 2) thresh = v;
    }
    __syncthreads();

    if (tid == 0) {
        int g = 0;
        grp[0] = 0;
        for (int tt = 1; tt < T_; tt++) {
            g += (nsv[tt - 1] <= thresh) ? 1 : 0;
            grp[tt] = g;
        }
    }
    __syncthreads();

    if (tid < EMB_ * NBINS_) {
        int ee = tid >> 2, k = tid & 3;
        float s = 0.0f;
        for (int tt = 0; tt < T_; tt++) if (grp[tt] == k) s += ne[ee][tt];
        csum[ee][k] = s;
    }
    if (tid < NBINS_) {
        float s = 0.0f;
        for (int tt = 0; tt < T_; tt++) s += (grp[tt] == tid) ? 1.0f : 0.0f;
        gsize[tid] = s;
    }
    __syncthreads();

    if (tid < NBINS_) {
        int k = tid;
        float gs = gsize[k];
        float inv_gs = (gs > 0.0f) ? (1.0f / gs) : 0.0f;
        float s = 0.0f;
        for (int ee = 0; ee < EMB_; ee++) { float v = csum[ee][k] * inv_gs; s += v * v; }
        float inv_n = 1.0f / fmaxf(sqrtf(s), 1e-12f);
        for (int ee = 0; ee < EMB_; ee++) ncen[ee][k] = csum[ee][k] * inv_gs * inv_n;
    }
    __syncthreads();

    if (tid < T_ * NBINS_) {
        int tt = tid >> 2, k = tid & 3;
        float s = 0.0f;
        for (int ee = 0; ee < EMB_; ee++) s += ne[ee][tt] * ncen[ee][k];
        wts[tt][k] = SCALE_ * s;
    }
    __syncthreads();

    if (tid < T_) {
        float s0 = wts[tid][0], s1 = wts[tid][1], s2 = wts[tid][2], s3 = wts[tid][3];
        float m = fmaxf(fmaxf(s0, s1), fmaxf(s2, s3));
        float e0 = expf(s0 - m), e1 = expf(s1 - m), e2 = expf(s2 - m), e3 = expf(s3 - m);
        float inv = 1.0f / (e0 + e1 + e2 + e3);
        wts[tid][0] = e0 * inv; wts[tid][1] = e1 * inv;
        wts[tid][2] = e2 * inv; wts[tid][3] = e3 * inv;
    }
    __syncthreads();

    if (tid < NBINS_) {
        float s = 0.0f;
        for (int tt = 0; tt < T_; tt++) s += wts[tt][tid];
        sscale[tid] = (s > 0.0f) ? (1.0f / s) : 1.0f;
    }
    __syncthreads();

    if (tid < T_ * NBINS_) {
        int tt = tid >> 2, k = tid & 3;
        g_nw[(size_t)b * T_ * NBINS_ + tt * NBINS_ + k] = wts[tt][k] * sscale[k];
    }
}

// ---------------------------------------------------------------------------
// Kernel 3 (R14 body, PDL): occ 4 -> 3 (85-reg budget) to deepen per-warp
// load batching. Prefetch first two x tiles pre-sync.
// ---------------------------------------------------------------------------
__global__ __launch_bounds__(256, 3)
void output_kernel(const float* __restrict__ x, float* __restrict__ out) {
    __shared__ float4 swt[B_ * T_];

    int gtid = blockIdx.x * blockDim.x + threadIdx.x;
    int bc = gtid / HW4_;
    int p  = gtid - bc * HW4_;
    bc = (B_ * C_ - 1) - bc;
    int b  = bc >> 8;  // /C_

    const float4* xr = reinterpret_cast<const float4*>(x) + (size_t)bc * T_ * HW4_ + p;
    float4 v0 = __ldcs(&xr[0]);
    float4 v1 = __ldcs(&xr[HW4_]);

    cudaGridDependencySynchronize();   // wait for weights_kernel
    {
        const float4* src = reinterpret_cast<const float4*>(g_nw);
        swt[threadIdx.x] = src[threadIdx.x];
    }
    __syncthreads();

    const float4* wb = swt + b * T_;
    float4 a0 = {0,0,0,0}, a1 = {0,0,0,0}, a2 = {0,0,0,0}, a3 = {0,0,0,0};
    {
        float4 w = wb[0];
        a0.x = fmaf(v0.x, w.x, a0.x); a0.y = fmaf(v0.y, w.x, a0.y);
        a0.z = fmaf(v0.z, w.x, a0.z); a0.w = fmaf(v0.w, w.x, a0.w);
        a1.x = fmaf(v0.x, w.y, a1.x); a1.y = fmaf(v0.y, w.y, a1.y);
        a1.z = fmaf(v0.z, w.y, a1.z); a1.w = fmaf(v0.w, w.y, a1.w);
        a2.x = fmaf(v0.x, w.z, a2.x); a2.y = fmaf(v0.y, w.z, a2.y);
        a2.z = fmaf(v0.z, w.z, a2.z); a2.w = fmaf(v0.w, w.z, a2.w);
        a3.x = fmaf(v0.x, w.w, a3.x); a3.y = fmaf(v0.y, w.w, a3.y);
        a3.z = fmaf(v0.z, w.w, a3.z); a3.w = fmaf(v0.w, w.w, a3.w);
    }
    {
        float4 w = wb[1];
        a0.x = fmaf(v1.x, w.x, a0.x); a0.y = fmaf(v1.y, w.x, a0.y);
        a0.z = fmaf(v1.z, w.x, a0.z); a0.w = fmaf(v1.w, w.x, a0.w);
        a1.x = fmaf(v1.x, w.y, a1.x); a1.y = fmaf(v1.y, w.y, a1.y);
        a1.z = fmaf(v1.z, w.y, a1.z); a1.w = fmaf(v1.w, w.y, a1.w);
        a2.x = fmaf(v1.x, w.z, a2.x); a2.y = fmaf(v1.y, w.z, a2.y);
        a2.z = fmaf(v1.z, w.z, a2.z); a2.w = fmaf(v1.w, w.z, a2.w);
        a3.x = fmaf(v1.x, w.w, a3.x); a3.y = fmaf(v1.y, w.w, a3.y);
        a3.z = fmaf(v1.z, w.w, a3.z); a3.w = fmaf(v1.w, w.w, a3.w);
    }
#pragma unroll
    for (int t = 2; t < T_; t++) {
        float4 v = __ldcs(&xr[(size_t)t * HW4_]);
        float4 w = wb[t];
        a0.x = fmaf(v.x, w.x, a0.x); a0.y = fmaf(v.y, w.x, a0.y);
        a0.z = fmaf(v.z, w.x, a0.z); a0.w = fmaf(v.w, w.x, a0.w);
        a1.x = fmaf(v.x, w.y, a1.x); a1.y = fmaf(v.y, w.y, a1.y);
        a1.z = fmaf(v.z, w.y, a1.z); a1.w = fmaf(v.w, w.y, a1.w);
        a2.x = fmaf(v.x, w.z, a2.x); a2.y = fmaf(v.y, w.z, a2.y);
        a2.z = fmaf(v.z, w.z, a2.z); a2.w = fmaf(v.w, w.z, a2.w);
        a3.x = fmaf(v.x, w.w, a3.x); a3.y = fmaf(v.y, w.w, a3.y);
        a3.z = fmaf(v.z, w.w, a3.z); a3.w = fmaf(v.w, w.w, a3.w);
    }
    float4* o = reinterpret_cast<float4*>(out) + (size_t)bc * NBINS_ * HW4_ + p;
    __stcs(&o[0 * HW4_], a0);
    __stcs(&o[1 * HW4_], a1);
    __stcs(&o[2 * HW4_], a2);
    __stcs(&o[3 * HW4_], a3);
}

// ---------------------------------------------------------------------------
// Launch (R14-exact): linear single-stream graph; PDL on the three consumers.
// ---------------------------------------------------------------------------
extern "C" void kernel_launch(void* const* d_in, const int* in_sizes, int n_in,
                              void* d_out, int out_size) {
    const float* x  = (const float*)d_in[0];
    const float* W1 = (const float*)d_in[1];
    const float* b1 = (const float*)d_in[2];
    const float* W2 = (const float*)d_in[3];
    const float* b2 = (const float*)d_in[4];
    float* out = (float*)d_out;

    const int WSMEM = (HID_ * T_ + EMB_ * HID_) * (int)sizeof(float);

    static int init_done = 0;
    if (!init_done) {
        cudaFuncSetAttribute(weights_kernel,
                             cudaFuncAttributeMaxDynamicSharedMemorySize, WSMEM);
        init_done = 1;
    }

    pool_kernel<<<(B_ * C_ * T_) / 8, 256>>>(x);

    cudaLaunchAttribute attrs[1];
    attrs[0].id = cudaLaunchAttributeProgrammaticStreamSerialization;
    attrs[0].val.programmaticStreamSerializationAllowed = 1;

    cudaLaunchConfig_t cfg = {};
    cfg.stream = 0;
    cfg.attrs = attrs;
    cfg.numAttrs = 1;

    cfg.gridDim = dim3(B_ * 16);       // 128 blocks
    cfg.blockDim = dim3(1024);
    cfg.dynamicSmemBytes = 0;
    cudaLaunchKernelEx(&cfg, mlp1_kernel, W1, b1);

    cfg.gridDim = dim3(B_);
    cfg.blockDim = dim3(1024);
    cfg.dynamicSmemBytes = WSMEM;
    cudaLaunchKernelEx(&cfg, weights_kernel, W2, b2);

    int total = B_ * C_ * HW4_;
    cfg.gridDim = dim3(total / 256);   // 1568, exact
    cfg.blockDim = dim3(256);
    cfg.dynamicSmemBytes = 0;
    cudaLaunchKernelEx(&cfg, output_kernel, x, out);
}

// round 17
// speedup vs baseline: 1.0097x; 1.0097x over previous
#include <cuda_runtime.h>
#include <cuda_bf16.h>
#include <math.h>

// Problem constants
#define B_  8
#define C_  256
#define T_  32
#define HW_ 784            // 28*28
#define HW4_ 196           // HW/4
#define HID_ 512
#define EMB_ 32
#define NBINS_ 4
#define SCALE_ 5.0f

// Scratch (device globals — no allocation allowed)
__device__ float g_pooled[B_ * C_ * T_];   // [B,C,T]
__device__ float g_h[B_ * HID_ * T_];      // [B,HID,T]
__device__ float g_nw[B_ * T_ * NBINS_];   // [B,T,4] => float4 per (b,t)

// ---------------------------------------------------------------------------
// Kernel 1 (R14-exact): spatial mean pool. One warp per (b,c,t) row, __ldcs.
// ---------------------------------------------------------------------------
__global__ void pool_kernel(const float* __restrict__ x) {
    int warp = (blockIdx.x * blockDim.x + threadIdx.x) >> 5;
    int lane = threadIdx.x & 31;
    const float4* row = reinterpret_cast<const float4*>(x) + (size_t)warp * HW4_;
    float4 v0 = __ldcs(&row[lane]);
    float4 v1 = __ldcs(&row[lane + 32]);
    float4 v2 = __ldcs(&row[lane + 64]);
    float4 v3 = __ldcs(&row[lane + 96]);
    float4 v4 = __ldcs(&row[lane + 128]);
    float4 v5 = __ldcs(&row[lane + 160]);
    float4 v6 = (lane < 4) ? __ldcs(&row[lane + 192]) : make_float4(0.f, 0.f, 0.f, 0.f);
    float s = (v0.x + v0.y) + (v0.z + v0.w);
    s += (v1.x + v1.y) + (v1.z + v1.w);
    s += (v2.x + v2.y) + (v2.z + v2.w);
    s += (v3.x + v3.y) + (v3.z + v3.w);
    s += (v4.x + v4.y) + (v4.z + v4.w);
    s += (v5.x + v5.y) + (v5.z + v5.w);
    s += (v6.x + v6.y) + (v6.z + v6.w);
#pragma unroll
    for (int o = 16; o > 0; o >>= 1) s += __shfl_xor_sync(0xFFFFFFFFu, s, o);
    if (lane == 0) g_pooled[warp] = s * (1.0f / (float)HW_);
}

// ---------------------------------------------------------------------------
// Kernel 2a (R14-exact, PDL): h = hswish(W1 @ pooled + b1).
// ---------------------------------------------------------------------------
__global__ __launch_bounds__(1024)
void mlp1_kernel(const float* __restrict__ W1, const float* __restrict__ b1) {
    __shared__ float sp[C_ * T_];    // 32 KB
    __shared__ float sw[32 * C_];    // 32 KB
    int b = blockIdx.x >> 4;                 // /16
    int hid0 = (blockIdx.x & 15) * 32;
    int tid = threadIdx.x;
    {
        const float4* src = reinterpret_cast<const float4*>(W1 + (size_t)hid0 * C_);
        float4* dst = reinterpret_cast<float4*>(sw);
        dst[tid] = src[tid];
        dst[tid + 1024] = src[tid + 1024];
    }
    cudaGridDependencySynchronize();   // wait for pool_kernel
    {
        const float4* src = reinterpret_cast<const float4*>(g_pooled + (size_t)b * C_ * T_);
        float4* dst = reinterpret_cast<float4*>(sp);
        dst[tid] = src[tid];
        dst[tid + 1024] = src[tid + 1024];
    }
    __syncthreads();

    int w = tid >> 5;
    int lane = tid & 31;
    int hid = hid0 + w;
    const float* wr = sw + w * C_;
    float a0 = 0.f, a1 = 0.f, a2 = 0.f, a3 = 0.f;
#pragma unroll 8
    for (int c = 0; c < C_; c += 4) {
        float4 wv = *reinterpret_cast<const float4*>(wr + c);
        a0 = fmaf(wv.x, sp[(c + 0) * T_ + lane], a0);
        a1 = fmaf(wv.y, sp[(c + 1) * T_ + lane], a1);
        a2 = fmaf(wv.z, sp[(c + 2) * T_ + lane], a2);
        a3 = fmaf(wv.w, sp[(c + 3) * T_ + lane], a3);
    }
    float acc = ((a0 + a1) + (a2 + a3)) + b1[hid];
    float g = fminf(fmaxf(acc + 3.0f, 0.0f), 6.0f);
    acc = acc * g * (1.0f / 6.0f);
    g_h[((size_t)b * HID_ + hid) * T_ + lane] = acc;
}

// ---------------------------------------------------------------------------
// Kernel 2b (PDL): embds with INDEPENDENT lane accumulators — each e keeps 4
// partial sums (one per float4 lane), so dependent-FMA chains are 128 long
// instead of 512. Reduced at the end. Rest is R14-exact.
// ---------------------------------------------------------------------------
extern __shared__ float dynsm[];   // [0:16384)=h [hid][t], [16384:32768)=W2 [e][hh]

__global__ __launch_bounds__(1024, 1)
void weights_kernel(const float* __restrict__ W2, const float* __restrict__ b2) {
    __shared__ float ne[EMB_][T_ + 1];
    __shared__ float invn[T_];
    __shared__ float nsv[T_];
    __shared__ float thresh;
    __shared__ int   grp[T_];
    __shared__ float csum[EMB_][NBINS_];
    __shared__ float gsize[NBINS_];
    __shared__ float ncen[EMB_][NBINS_];
    __shared__ float wts[T_][NBINS_];
    __shared__ float sscale[NBINS_];

    int b = blockIdx.x;
    int tid = threadIdx.x;
    float* sh  = dynsm;
    float* sw2 = dynsm + HID_ * T_;

    {
        const float4* wsrc = reinterpret_cast<const float4*>(W2);
        float4* wdst = reinterpret_cast<float4*>(sw2);
#pragma unroll
        for (int i = 0; i < 4; i++) wdst[tid + i * 1024] = wsrc[tid + i * 1024];
    }
    cudaGridDependencySynchronize();   // wait for mlp1_kernel
    {
        const float4* hsrc = reinterpret_cast<const float4*>(g_h + (size_t)b * HID_ * T_);
        float4* hdst = reinterpret_cast<float4*>(sh);
#pragma unroll
        for (int i = 0; i < 4; i++) hdst[tid + i * 1024] = hsrc[tid + i * 1024];
    }
    __syncthreads();

    if (tid < 256) {
        int t = tid & 31;
        int eg = tid >> 5;
        // 4 e's per thread, each with 4 independent partial accumulators
        float4 a0 = {0,0,0,0}, a1 = {0,0,0,0}, a2 = {0,0,0,0}, a3 = {0,0,0,0};
        const float* w0 = sw2 + (size_t)(4 * eg + 0) * HID_;
        const float* w1 = sw2 + (size_t)(4 * eg + 1) * HID_;
        const float* w2r = sw2 + (size_t)(4 * eg + 2) * HID_;
        const float* w3 = sw2 + (size_t)(4 * eg + 3) * HID_;
#pragma unroll 4
        for (int hh = 0; hh < HID_; hh += 4) {
            float h0 = sh[(hh + 0) * T_ + t];
            float h1 = sh[(hh + 1) * T_ + t];
            float h2 = sh[(hh + 2) * T_ + t];
            float h3 = sh[(hh + 3) * T_ + t];
            float4 w0v = *reinterpret_cast<const float4*>(w0 + hh);
            float4 w1v = *reinterpret_cast<const float4*>(w1 + hh);
            float4 w2v = *reinterpret_cast<const float4*>(w2r + hh);
            float4 w3v = *reinterpret_cast<const float4*>(w3 + hh);
            a0.x = fmaf(w0v.x, h0, a0.x); a0.y = fmaf(w0v.y, h1, a0.y);
            a0.z = fmaf(w0v.z, h2, a0.z); a0.w = fmaf(w0v.w, h3, a0.w);
            a1.x = fmaf(w1v.x, h0, a1.x); a1.y = fmaf(w1v.y, h1, a1.y);
            a1.z = fmaf(w1v.z, h2, a1.z); a1.w = fmaf(w1v.w, h3, a1.w);
            a2.x = fmaf(w2v.x, h0, a2.x); a2.y = fmaf(w2v.y, h1, a2.y);
            a2.z = fmaf(w2v.z, h2, a2.z); a2.w = fmaf(w2v.w, h3, a2.w);
            a3.x = fmaf(w3v.x, h0, a3.x); a3.y = fmaf(w3v.y, h1, a3.y);
            a3.z = fmaf(w3v.z, h2, a3.z); a3.w = fmaf(w3v.w, h3, a3.w);
        }
        ne[4 * eg + 0][t] = ((a0.x + a0.y) + (a0.z + a0.w)) + b2[4 * eg + 0];
        ne[4 * eg + 1][t] = ((a1.x + a1.y) + (a1.z + a1.w)) + b2[4 * eg + 1];
        ne[4 * eg + 2][t] = ((a2.x + a2.y) + (a2.z + a2.w)) + b2[4 * eg + 2];
        ne[4 * eg + 3][t] = ((a3.x + a3.y) + (a3.z + a3.w)) + b2[4 * eg + 3];
    }
    __syncthreads();

    if (tid < T_) {
        float s = 0.0f;
        for (int ee = 0; ee < EMB_; ee++) { float v = ne[ee][tid]; s += v * v; }
        invn[tid] = 1.0f / fmaxf(sqrtf(s), 1e-12f);
    }
    __syncthreads();
    {
        int e = tid >> 5, t = tid & 31;
        ne[e][t] *= invn[t];
    }
    __syncthreads();

    if (tid < T_ - 1) {
        float s = 0.0f;
        for (int ee = 0; ee < EMB_; ee++) s += ne[ee][tid + 1] * ne[ee][tid];
        nsv[tid] = s;
    }
    __syncthreads();

    if (tid < T_ - 1) {
        float v = nsv[tid];
        int cnt = 0;
        for (int j = 0; j < T_ - 1; j++) {
            float o = nsv[j];
            cnt += (o < v) || (o == v && j < tid);
        }
        if (cnt == 2) thresh = v;
    }
    __syncthreads();

    if (tid == 0) {
        int g = 0;
        grp[0] = 0;
        for (int tt = 1; tt < T_; tt++) {
            g += (nsv[tt - 1] <= thresh) ? 1 : 0;
            grp[tt] = g;
        }
    }
    __syncthreads();

    if (tid < EMB_ * NBINS_) {
        int ee = tid >> 2, k = tid & 3;
        float s = 0.0f;
        for (int tt = 0; tt < T_; tt++) if (grp[tt] == k) s += ne[ee][tt];
        csum[ee][k] = s;
    }
    if (tid < NBINS_) {
        float s = 0.0f;
        for (int tt = 0; tt < T_; tt++) s += (grp[tt] == tid) ? 1.0f : 0.0f;
        gsize[tid] = s;
    }
    __syncthreads();

    if (tid < NBINS_) {
        int k = tid;
        float gs = gsize[k];
        float inv_gs = (gs > 0.0f) ? (1.0f / gs) : 0.0f;
        float s = 0.0f;
        for (int ee = 0; ee < EMB_; ee++) { float v = csum[ee][k] * inv_gs; s += v * v; }
        float inv_n = 1.0f / fmaxf(sqrtf(s), 1e-12f);
        for (int ee = 0; ee < EMB_; ee++) ncen[ee][k] = csum[ee][k] * inv_gs * inv_n;
    }
    __syncthreads();

    if (tid < T_ * NBINS_) {
        int tt = tid >> 2, k = tid & 3;
        float s = 0.0f;
        for (int ee = 0; ee < EMB_; ee++) s += ne[ee][tt] * ncen[ee][k];
        wts[tt][k] = SCALE_ * s;
    }
    __syncthreads();

    if (tid < T_) {
        float s0 = wts[tid][0], s1 = wts[tid][1], s2 = wts[tid][2], s3 = wts[tid][3];
        float m = fmaxf(fmaxf(s0, s1), fmaxf(s2, s3));
        float e0 = expf(s0 - m), e1 = expf(s1 - m), e2 = expf(s2 - m), e3 = expf(s3 - m);
        float inv = 1.0f / (e0 + e1 + e2 + e3);
        wts[tid][0] = e0 * inv; wts[tid][1] = e1 * inv;
        wts[tid][2] = e2 * inv; wts[tid][3] = e3 * inv;
    }
    __syncthreads();

    if (tid < NBINS_) {
        float s = 0.0f;
        for (int tt = 0; tt < T_; tt++) s += wts[tt][tid];
        sscale[tid] = (s > 0.0f) ? (1.0f / s) : 1.0f;
    }
    __syncthreads();

    if (tid < T_ * NBINS_) {
        int tt = tid >> 2, k = tid & 3;
        g_nw[(size_t)b * T_ * NBINS_ + tt * NBINS_ + k] = wts[tt][k] * sscale[k];
    }
}

// ---------------------------------------------------------------------------
// Kernel 3 (R14-exact, PDL): 64 regs / occ 4; prefetch first two x tiles.
// ---------------------------------------------------------------------------
__global__ __launch_bounds__(256, 4)
void output_kernel(const float* __restrict__ x, float* __restrict__ out) {
    __shared__ float4 swt[B_ * T_];

    int gtid = blockIdx.x * blockDim.x + threadIdx.x;
    int bc = gtid / HW4_;
    int p  = gtid - bc * HW4_;
    bc = (B_ * C_ - 1) - bc;
    int b  = bc >> 8;  // /C_

    const float4* xr = reinterpret_cast<const float4*>(x) + (size_t)bc * T_ * HW4_ + p;
    float4 v0 = __ldcs(&xr[0]);
    float4 v1 = __ldcs(&xr[HW4_]);

    cudaGridDependencySynchronize();   // wait for weights_kernel
    {
        const float4* src = reinterpret_cast<const float4*>(g_nw);
        swt[threadIdx.x] = src[threadIdx.x];
    }
    __syncthreads();

    const float4* wb = swt + b * T_;
    float4 a0 = {0,0,0,0}, a1 = {0,0,0,0}, a2 = {0,0,0,0}, a3 = {0,0,0,0};
    {
        float4 w = wb[0];
        a0.x = fmaf(v0.x, w.x, a0.x); a0.y = fmaf(v0.y, w.x, a0.y);
        a0.z = fmaf(v0.z, w.x, a0.z); a0.w = fmaf(v0.w, w.x, a0.w);
        a1.x = fmaf(v0.x, w.y, a1.x); a1.y = fmaf(v0.y, w.y, a1.y);
        a1.z = fmaf(v0.z, w.y, a1.z); a1.w = fmaf(v0.w, w.y, a1.w);
        a2.x = fmaf(v0.x, w.z, a2.x); a2.y = fmaf(v0.y, w.z, a2.y);
        a2.z = fmaf(v0.z, w.z, a2.z); a2.w = fmaf(v0.w, w.z, a2.w);
        a3.x = fmaf(v0.x, w.w, a3.x); a3.y = fmaf(v0.y, w.w, a3.y);
        a3.z = fmaf(v0.z, w.w, a3.z); a3.w = fmaf(v0.w, w.w, a3.w);
    }
    {
        float4 w = wb[1];
        a0.x = fmaf(v1.x, w.x, a0.x); a0.y = fmaf(v1.y, w.x, a0.y);
        a0.z = fmaf(v1.z, w.x, a0.z); a0.w = fmaf(v1.w, w.x, a0.w);
        a1.x = fmaf(v1.x, w.y, a1.x); a1.y = fmaf(v1.y, w.y, a1.y);
        a1.z = fmaf(v1.z, w.y, a1.z); a1.w = fmaf(v1.w, w.y, a1.w);
        a2.x = fmaf(v1.x, w.z, a2.x); a2.y = fmaf(v1.y, w.z, a2.y);
        a2.z = fmaf(v1.z, w.z, a2.z); a2.w = fmaf(v1.w, w.z, a2.w);
        a3.x = fmaf(v1.x, w.w, a3.x); a3.y = fmaf(v1.y, w.w, a3.y);
        a3.z = fmaf(v1.z, w.w, a3.z); a3.w = fmaf(v1.w, w.w, a3.w);
    }
#pragma unroll
    for (int t = 2; t < T_; t++) {
        float4 v = __ldcs(&xr[(size_t)t * HW4_]);
        float4 w = wb[t];
        a0.x = fmaf(v.x, w.x, a0.x); a0.y = fmaf(v.y, w.x, a0.y);
        a0.z = fmaf(v.z, w.x, a0.z); a0.w = fmaf(v.w, w.x, a0.w);
        a1.x = fmaf(v.x, w.y, a1.x); a1.y = fmaf(v.y, w.y, a1.y);
        a1.z = fmaf(v.z, w.y, a1.z); a1.w = fmaf(v.w, w.y, a1.w);
        a2.x = fmaf(v.x, w.z, a2.x); a2.y = fmaf(v.y, w.z, a2.y);
        a2.z = fmaf(v.z, w.z, a2.z); a2.w = fmaf(v.w, w.z, a2.w);
        a3.x = fmaf(v.x, w.w, a3.x); a3.y = fmaf(v.y, w.w, a3.y);
        a3.z = fmaf(v.z, w.w, a3.z); a3.w = fmaf(v.w, w.w, a3.w);
    }
    float4* o = reinterpret_cast<float4*>(out) + (size_t)bc * NBINS_ * HW4_ + p;
    __stcs(&o[0 * HW4_], a0);
    __stcs(&o[1 * HW4_], a1);
    __stcs(&o[2 * HW4_], a2);
    __stcs(&o[3 * HW4_], a3);
}

// ---------------------------------------------------------------------------
// Launch (R14-exact): linear single-stream graph; PDL on the three consumers.
// ---------------------------------------------------------------------------
extern "C" void kernel_launch(void* const* d_in, const int* in_sizes, int n_in,
                              void* d_out, int out_size) {
    const float* x  = (const float*)d_in[0];
    const float* W1 = (const float*)d_in[1];
    const float* b1 = (const float*)d_in[2];
    const float* W2 = (const float*)d_in[3];
    const float* b2 = (const float*)d_in[4];
    float* out = (float*)d_out;

    const int WSMEM = (HID_ * T_ + EMB_ * HID_) * (int)sizeof(float);

    static int init_done = 0;
    if (!init_done) {
        cudaFuncSetAttribute(weights_kernel,
                             cudaFuncAttributeMaxDynamicSharedMemorySize, WSMEM);
        init_done = 1;
    }

    pool_kernel<<<(B_ * C_ * T_) / 8, 256>>>(x);

    cudaLaunchAttribute attrs[1];
    attrs[0].id = cudaLaunchAttributeProgrammaticStreamSerialization;
    attrs[0].val.programmaticStreamSerializationAllowed = 1;

    cudaLaunchConfig_t cfg = {};
    cfg.stream = 0;
    cfg.attrs = attrs;
    cfg.numAttrs = 1;

    cfg.gridDim = dim3(B_ * 16);       // 128 blocks
    cfg.blockDim = dim3(1024);
    cfg.dynamicSmemBytes = 0;
    cudaLaunchKernelEx(&cfg, mlp1_kernel, W1, b1);

    cfg.gridDim = dim3(B_);
    cfg.blockDim = dim3(1024);
    cfg.dynamicSmemBytes = WSMEM;
    cudaLaunchKernelEx(&cfg, weights_kernel, W2, b2);

    int total = B_ * C_ * HW4_;
    cfg.gridDim = dim3(total / 256);   // 1568, exact
    cfg.blockDim = dim3(256);
    cfg.dynamicSmemBytes = 0;
    cudaLaunchKernelEx(&cfg, output_kernel, x, out);
}